// round 10
// baseline (speedup 1.0000x reference)
#include <cuda_runtime.h>

#define NX     768
#define NHEAD  12
#define SEQ    2048
#define HD     64
#define BS     2
#define QKV3   (3 * NX)

typedef unsigned long long ull;

// packed f32x2 helpers (FFMA2 is only reachable via PTX)
#define FMA2(d, a, b, c) \
    asm("fma.rn.f32x2 %0, %1, %2, %3;" : "=l"(d) : "l"(a), "l"(b), "l"(c))
#define MUL2(d, a, b) \
    asm("mul.rn.f32x2 %0, %1, %2;" : "=l"(d) : "l"(a), "l"(b))
#define PACK2(d, lo, hi) \
    asm("mov.b64 %0, {%1, %2};" : "=l"(d) : "f"(lo), "f"(hi))
#define UNPACK2(lo, hi, d) \
    asm("mov.b64 {%0, %1}, %2;" : "=f"(lo), "=f"(hi) : "l"(d))

// Scratch (no cudaMalloc allowed)
__device__ float g_qkv[(size_t)BS * SEQ * QKV3];
__device__ float g_attn[(size_t)BS * SEQ * NX];

// ---------------------------------------------------------------------------
// C[M,N] = A[M,K] @ B[K,N] + bias[N]
// BM=BN=128, BK=16, 256 threads, 8x8 microtile, scalar FFMA.
// Per kk: 4 x LDS.128 -> 64 FMA (2x the FLOP/byte of the R5 8x4 tile).
// ---------------------------------------------------------------------------
__global__ __launch_bounds__(256) void gemm_bias_kernel(
    const float* __restrict__ A, const float* __restrict__ B,
    const float* __restrict__ bias, float* __restrict__ C,
    int M, int N, int K)
{
    constexpr int BM = 128, BN = 128, BK = 16;
    __shared__ float As[BK][BM + 4];   // transposed, padded (8.25 KB)
    __shared__ float Bs[BK][BN];       // (8 KB)

    const int tid = threadIdx.x;
    const int tx = tid & 15;           // 0..15 -> 8 cols each
    const int ty = tid >> 4;           // 0..15 -> 8 rows each
    const int row0 = blockIdx.y * BM;
    const int col0 = blockIdx.x * BN;

    float acc[8][8] = {};

    for (int k0 = 0; k0 < K; k0 += BK) {
        // A tile: 128x16 = 512 float4; 2 per thread; store transposed
        #pragma unroll
        for (int i = tid; i < BM * BK / 4; i += 256) {
            int r  = i >> 2;
            int c4 = i & 3;
            float4 t = *(const float4*)&A[(size_t)(row0 + r) * K + k0 + c4 * 4];
            As[c4 * 4 + 0][r] = t.x;
            As[c4 * 4 + 1][r] = t.y;
            As[c4 * 4 + 2][r] = t.z;
            As[c4 * 4 + 3][r] = t.w;
        }
        // B tile: 16x128 = 512 float4; 2 per thread
        #pragma unroll
        for (int i = tid; i < BK * BN / 4; i += 256) {
            int r = i >> 5;
            int c = i & 31;
            *(float4*)&Bs[r][c * 4] =
                *(const float4*)&B[(size_t)(k0 + r) * N + col0 + c * 4];
        }
        __syncthreads();

        #pragma unroll
        for (int kk = 0; kk < BK; kk++) {
            float4 a0 = *(const float4*)&As[kk][ty * 8];
            float4 a1 = *(const float4*)&As[kk][ty * 8 + 4];
            float4 b0 = *(const float4*)&Bs[kk][tx * 8];
            float4 b1 = *(const float4*)&Bs[kk][tx * 8 + 4];
            float a[8] = {a0.x, a0.y, a0.z, a0.w, a1.x, a1.y, a1.z, a1.w};
            float bb[8] = {b0.x, b0.y, b0.z, b0.w, b1.x, b1.y, b1.z, b1.w};
            #pragma unroll
            for (int i = 0; i < 8; i++)
                #pragma unroll
                for (int j = 0; j < 8; j++)
                    acc[i][j] += a[i] * bb[j];
        }
        __syncthreads();
    }

    float4 bi0 = *(const float4*)&bias[col0 + tx * 8];
    float4 bi1 = *(const float4*)&bias[col0 + tx * 8 + 4];
    #pragma unroll
    for (int i = 0; i < 8; i++) {
        int r = row0 + ty * 8 + i;
        float4 o0 = {acc[i][0] + bi0.x, acc[i][1] + bi0.y,
                     acc[i][2] + bi0.z, acc[i][3] + bi0.w};
        float4 o1 = {acc[i][4] + bi1.x, acc[i][5] + bi1.y,
                     acc[i][6] + bi1.z, acc[i][7] + bi1.w};
        *(float4*)&C[(size_t)r * N + col0 + tx * 8]     = o0;
        *(float4*)&C[(size_t)r * N + col0 + tx * 8 + 4] = o1;
    }
}

// ---------------------------------------------------------------------------
// Flash attention, "raw reshape" layout, f32x2 inner loops.
// 2 threads per query row: thread (row, half) owns dims [half*32, half*32+32).
// Halves the per-thread register footprint -> 2x occupancy.
// q[b,h,s,d] = qkv[b][u/12][(u%12)*64 + d],  u = h*2048 + s
// k: +768; v: +1536. out[b,s,h*64+d].
// ---------------------------------------------------------------------------
__global__ __launch_bounds__(256) void attn_kernel(
    const float* __restrict__ qkv, const float* __restrict__ amask,
    float* __restrict__ attn_out)
{
    constexpr int BM = 128, BN = 32;
    constexpr int HH = HD / 2;         // 32 dims per thread
    const int qb   = blockIdx.x;
    const int h    = blockIdx.y;
    const int b    = blockIdx.z;
    const int tid  = threadIdx.x;
    const int row  = tid >> 1;
    const int half = tid & 1;
    const int qidx = qb * BM + row;

    __shared__ float Ks[BN][HD];
    __shared__ float Vs[BN][HD];
    __shared__ float Ams[SEQ];

    const float* base = qkv + (size_t)b * SEQ * QKV3;

    for (int i = tid; i < SEQ; i += 256) Ams[i] = amask[b * SEQ + i];

    // q half: 32 floats = 16 packed pairs (contiguous, 16B-aligned in gmem)
    ull q2[HH / 2];
    {
        int u = h * SEQ + qidx;
        const ulonglong2* qp = (const ulonglong2*)
            (base + (u / 12) * QKV3 + (u % 12) * HD + half * HH);
        #pragma unroll
        for (int i = 0; i < HH / 4; i++) {   // 8 x 16B
            ulonglong2 t = qp[i];
            q2[2 * i]     = t.x;
            q2[2 * i + 1] = t.y;
        }
    }

    ull acc2[HH / 2];
    #pragma unroll
    for (int d = 0; d < HH / 2; d++) acc2[d] = 0ull;
    float m = -3.0e38f, l = 0.f;

    const int nkb = (qb * BM + BM) / BN;   // causal
    for (int kb = 0; kb < nkb; kb++) {
        const int k0 = kb * BN;
        __syncthreads();   // protect previous iteration's Ks/Vs reads
        #pragma unroll
        for (int i = tid; i < BN * HD / 4; i += 256) {
            int j  = i >> 4;
            int d4 = i & 15;
            int u = h * SEQ + k0 + j;
            const float* rowbase = base + (u / 12) * QKV3 + (u % 12) * HD + d4 * 4;
            ((float4*)Ks)[i] = *(const float4*)(rowbase + NX);       // K
            ((float4*)Vs)[i] = *(const float4*)(rowbase + 2 * NX);   // V
        }
        __syncthreads();

        float s[BN];
        #pragma unroll
        for (int j = 0; j < BN; j++) {
            const ulonglong2* kp = (const ulonglong2*)(Ks[j] + half * HH);
            ull c0 = 0ull, c1 = 0ull, c2 = 0ull, c3 = 0ull;
            #pragma unroll
            for (int i = 0; i < HH / 8; i++) {   // 4 iters x 4 FMA2
                ulonglong2 kv0 = kp[2 * i];
                ulonglong2 kv1 = kp[2 * i + 1];
                FMA2(c0, q2[4 * i + 0], kv0.x, c0);
                FMA2(c1, q2[4 * i + 1], kv0.y, c1);
                FMA2(c2, q2[4 * i + 2], kv1.x, c2);
                FMA2(c3, q2[4 * i + 3], kv1.y, c3);
            }
            float f0, f1, f2, f3, f4, f5, f6, f7;
            UNPACK2(f0, f1, c0); UNPACK2(f2, f3, c1);
            UNPACK2(f4, f5, c2); UNPACK2(f6, f7, c3);
            float sum = ((f0 + f1) + (f2 + f3)) + ((f4 + f5) + (f6 + f7));
            sum += __shfl_xor_sync(0xffffffffu, sum, 1);   // combine halves
            int k = k0 + j;
            s[j] = (k <= qidx) ? (sum * 0.125f + Ams[k]) : (-10000.f + Ams[k]);
        }

        float mb = s[0];
        #pragma unroll
        for (int j = 1; j < BN; j++) mb = fmaxf(mb, s[j]);
        float mn = fmaxf(m, mb);
        float corr = __expf(m - mn);
        l *= corr;
        ull corr2;
        PACK2(corr2, corr, corr);
        #pragma unroll
        for (int d = 0; d < HH / 2; d++) MUL2(acc2[d], acc2[d], corr2);

        #pragma unroll
        for (int j = 0; j < BN; j++) {
            float p = __expf(s[j] - mn);
            l += p;
            ull pp;
            PACK2(pp, p, p);
            const ulonglong2* vp = (const ulonglong2*)(Vs[j] + half * HH);
            #pragma unroll
            for (int i = 0; i < HH / 4; i++) {
                ulonglong2 vv = vp[i];
                FMA2(acc2[2 * i],     pp, vv.x, acc2[2 * i]);
                FMA2(acc2[2 * i + 1], pp, vv.y, acc2[2 * i + 1]);
            }
        }
        m = mn;
    }

    float inv = 1.f / l;   // same in both halves (s, m, l identical)
    ull inv2;
    PACK2(inv2, inv, inv);
    ulonglong2* op = (ulonglong2*)
        (attn_out + ((size_t)b * SEQ + qidx) * NX + h * HD + half * HH);
    #pragma unroll
    for (int i = 0; i < HH / 4; i++) {
        ulonglong2 t;
        MUL2(t.x, acc2[2 * i],     inv2);
        MUL2(t.y, acc2[2 * i + 1], inv2);
        op[i] = t;
    }
}

// ---------------------------------------------------------------------------
extern "C" void kernel_launch(void* const* d_in, const int* in_sizes, int n_in,
                              void* d_out, int out_size)
{
    const float* hidden = (const float*)d_in[0];
    const float* amask  = (const float*)d_in[1];
    const float* w_attn = (const float*)d_in[2];
    const float* b_attn = (const float*)d_in[3];
    const float* w_proj = (const float*)d_in[4];
    const float* b_proj = (const float*)d_in[5];
    float* out = (float*)d_out;

    float *qkv, *attn;
    cudaGetSymbolAddress((void**)&qkv,  g_qkv);
    cudaGetSymbolAddress((void**)&attn, g_attn);

    const int M = BS * SEQ;   // 4096

    gemm_bias_kernel<<<dim3(QKV3 / 128, M / 128), 256>>>(hidden, w_attn, b_attn, qkv, M, QKV3, NX);

    attn_kernel<<<dim3(SEQ / 128, NHEAD, BS), 256>>>(qkv, amask, attn);

    gemm_bias_kernel<<<dim3(NX / 128, M / 128), 256>>>(attn, w_proj, b_proj, out, M, NX, NX);
}

// round 11
// speedup vs baseline: 1.4959x; 1.4959x over previous
#include <cuda_runtime.h>

#define NX     768
#define NHEAD  12
#define SEQ    2048
#define HD     64
#define BS     2
#define QKV3   (3 * NX)

typedef unsigned long long ull;

// packed f32x2 helpers (FFMA2 is only reachable via PTX)
#define FMA2(d, a, b, c) \
    asm("fma.rn.f32x2 %0, %1, %2, %3;" : "=l"(d) : "l"(a), "l"(b), "l"(c))
#define MUL2(d, a, b) \
    asm("mul.rn.f32x2 %0, %1, %2;" : "=l"(d) : "l"(a), "l"(b))
#define ADD2(d, a, b) \
    asm("add.rn.f32x2 %0, %1, %2;" : "=l"(d) : "l"(a), "l"(b))
#define PACK2(d, lo, hi) \
    asm("mov.b64 %0, {%1, %2};" : "=l"(d) : "f"(lo), "f"(hi))
#define UNPACK2(lo, hi, d) \
    asm("mov.b64 {%0, %1}, %2;" : "=f"(lo), "=f"(hi) : "l"(d))

// Scratch (no cudaMalloc allowed)
__device__ float g_qkv[(size_t)BS * SEQ * QKV3];
__device__ float g_attn[(size_t)BS * SEQ * NX];

// ---------------------------------------------------------------------------
// C[M,N] = A[M,K] @ B[K,N] + bias[N]
// BM=BN=128, BK=16, 256 threads, 8x8 microtile, scalar FFMA.  (R10, 318us)
// ---------------------------------------------------------------------------
__global__ __launch_bounds__(256) void gemm_bias_kernel(
    const float* __restrict__ A, const float* __restrict__ B,
    const float* __restrict__ bias, float* __restrict__ C,
    int M, int N, int K)
{
    constexpr int BM = 128, BN = 128, BK = 16;
    __shared__ float As[BK][BM + 4];   // transposed, padded
    __shared__ float Bs[BK][BN];

    const int tid = threadIdx.x;
    const int tx = tid & 15;
    const int ty = tid >> 4;
    const int row0 = blockIdx.y * BM;
    const int col0 = blockIdx.x * BN;

    float acc[8][8] = {};

    for (int k0 = 0; k0 < K; k0 += BK) {
        #pragma unroll
        for (int i = tid; i < BM * BK / 4; i += 256) {
            int r  = i >> 2;
            int c4 = i & 3;
            float4 t = *(const float4*)&A[(size_t)(row0 + r) * K + k0 + c4 * 4];
            As[c4 * 4 + 0][r] = t.x;
            As[c4 * 4 + 1][r] = t.y;
            As[c4 * 4 + 2][r] = t.z;
            As[c4 * 4 + 3][r] = t.w;
        }
        #pragma unroll
        for (int i = tid; i < BK * BN / 4; i += 256) {
            int r = i >> 5;
            int c = i & 31;
            *(float4*)&Bs[r][c * 4] =
                *(const float4*)&B[(size_t)(k0 + r) * N + col0 + c * 4];
        }
        __syncthreads();

        #pragma unroll
        for (int kk = 0; kk < BK; kk++) {
            float4 a0 = *(const float4*)&As[kk][ty * 8];
            float4 a1 = *(const float4*)&As[kk][ty * 8 + 4];
            float4 b0 = *(const float4*)&Bs[kk][tx * 8];
            float4 b1 = *(const float4*)&Bs[kk][tx * 8 + 4];
            float a[8] = {a0.x, a0.y, a0.z, a0.w, a1.x, a1.y, a1.z, a1.w};
            float bb[8] = {b0.x, b0.y, b0.z, b0.w, b1.x, b1.y, b1.z, b1.w};
            #pragma unroll
            for (int i = 0; i < 8; i++)
                #pragma unroll
                for (int j = 0; j < 8; j++)
                    acc[i][j] += a[i] * bb[j];
        }
        __syncthreads();
    }

    float4 bi0 = *(const float4*)&bias[col0 + tx * 8];
    float4 bi1 = *(const float4*)&bias[col0 + tx * 8 + 4];
    #pragma unroll
    for (int i = 0; i < 8; i++) {
        int r = row0 + ty * 8 + i;
        float4 o0 = {acc[i][0] + bi0.x, acc[i][1] + bi0.y,
                     acc[i][2] + bi0.z, acc[i][3] + bi0.w};
        float4 o1 = {acc[i][4] + bi1.x, acc[i][5] + bi1.y,
                     acc[i][6] + bi1.z, acc[i][7] + bi1.w};
        *(float4*)&C[(size_t)r * N + col0 + tx * 8]     = o0;
        *(float4*)&C[(size_t)r * N + col0 + tx * 8 + 4] = o1;
    }
}

// ---------------------------------------------------------------------------
// Flash attention, "raw reshape" layout, f32x2 inner loops (R8 structure:
// one thread per query row, no cross-lane traffic).
// Work balancing: CTA x processes query blocks qb=x AND qb=15-x, so every
// CTA does exactly 17 key-tiles -> one uniform wave of 192 CTAs.
// q[b,h,s,d] = qkv[b][u/12][(u%12)*64 + d],  u = h*2048 + s
// k: +768; v: +1536. out[b,s,h*64+d].
// ---------------------------------------------------------------------------
__global__ __launch_bounds__(128) void attn_kernel(
    const float* __restrict__ qkv, const float* __restrict__ amask,
    float* __restrict__ attn_out)
{
    constexpr int BM = 128, BN = 32;
    constexpr int NQB = SEQ / BM;      // 16 query blocks
    const int h   = blockIdx.y;
    const int b   = blockIdx.z;
    const int tid = threadIdx.x;

    __shared__ float Ks[BN][HD];
    __shared__ float Vs[BN][HD];
    __shared__ float Ams[SEQ];

    const float* base = qkv + (size_t)b * SEQ * QKV3;

    for (int i = tid; i < SEQ; i += BM) Ams[i] = amask[b * SEQ + i];
    __syncthreads();

    #pragma unroll
    for (int pass = 0; pass < 2; pass++) {
        const int qb = pass == 0 ? (int)blockIdx.x : (NQB - 1 - (int)blockIdx.x);
        const int qidx = qb * BM + tid;

        // q as 32 packed pairs (row is contiguous & 256B-aligned in gmem)
        ull q2[HD / 2];
        {
            int u = h * SEQ + qidx;
            const ulonglong2* qp =
                (const ulonglong2*)(base + (u / 12) * QKV3 + (u % 12) * HD);
            #pragma unroll
            for (int i = 0; i < HD / 4; i++) {
                ulonglong2 t = qp[i];
                q2[2 * i]     = t.x;
                q2[2 * i + 1] = t.y;
            }
        }

        ull acc2[HD / 2];
        #pragma unroll
        for (int d = 0; d < HD / 2; d++) acc2[d] = 0ull;
        float m = -3.0e38f, l = 0.f;

        const int nkb = (qb * BM + BM) / BN;   // causal
        for (int kb = 0; kb < nkb; kb++) {
            const int k0 = kb * BN;
            __syncthreads();   // protect previous tile's Ks/Vs reads
            #pragma unroll
            for (int i = tid; i < BN * HD / 4; i += BM) {
                int j  = i >> 4;
                int d4 = i & 15;
                int u = h * SEQ + k0 + j;
                const float* rowbase =
                    base + (u / 12) * QKV3 + (u % 12) * HD + d4 * 4;
                ((float4*)Ks)[i] = *(const float4*)(rowbase + NX);       // K
                ((float4*)Vs)[i] = *(const float4*)(rowbase + 2 * NX);   // V
            }
            __syncthreads();

            float s[BN];
            #pragma unroll
            for (int j = 0; j < BN; j++) {
                const ulonglong2* kp = (const ulonglong2*)Ks[j];
                ull c0 = 0ull, c1 = 0ull, c2 = 0ull, c3 = 0ull;
                #pragma unroll
                for (int i = 0; i < 8; i++) {
                    ulonglong2 kv0 = kp[2 * i];
                    ulonglong2 kv1 = kp[2 * i + 1];
                    FMA2(c0, q2[4 * i + 0], kv0.x, c0);
                    FMA2(c1, q2[4 * i + 1], kv0.y, c1);
                    FMA2(c2, q2[4 * i + 2], kv1.x, c2);
                    FMA2(c3, q2[4 * i + 3], kv1.y, c3);
                }
                // packed tree reduction: 3 x ADD2 + 1 scalar add
                ull t01, t23, t;
                ADD2(t01, c0, c1);
                ADD2(t23, c2, c3);
                ADD2(t, t01, t23);
                float slo, shi;
                UNPACK2(slo, shi, t);
                float sum = slo + shi;
                int k = k0 + j;
                s[j] = (k <= qidx) ? (sum * 0.125f + Ams[k])
                                   : (-10000.f + Ams[k]);
            }

            float mb = s[0];
            #pragma unroll
            for (int j = 1; j < BN; j++) mb = fmaxf(mb, s[j]);
            float mn = fmaxf(m, mb);
            float corr = __expf(m - mn);
            l *= corr;
            ull corr2;
            PACK2(corr2, corr, corr);
            #pragma unroll
            for (int d = 0; d < HD / 2; d++) MUL2(acc2[d], acc2[d], corr2);

            #pragma unroll
            for (int j = 0; j < BN; j++) {
                float p = __expf(s[j] - mn);
                l += p;
                ull pp;
                PACK2(pp, p, p);
                const ulonglong2* vp = (const ulonglong2*)Vs[j];
                #pragma unroll
                for (int i = 0; i < HD / 4; i++) {
                    ulonglong2 vv = vp[i];
                    FMA2(acc2[2 * i],     pp, vv.x, acc2[2 * i]);
                    FMA2(acc2[2 * i + 1], pp, vv.y, acc2[2 * i + 1]);
                }
            }
            m = mn;
        }

        float inv = 1.f / l;
        ull inv2;
        PACK2(inv2, inv, inv);
        ulonglong2* op =
            (ulonglong2*)(attn_out + ((size_t)b * SEQ + qidx) * NX + h * HD);
        #pragma unroll
        for (int i = 0; i < HD / 4; i++) {
            ulonglong2 t;
            MUL2(t.x, acc2[2 * i],     inv2);
            MUL2(t.y, acc2[2 * i + 1], inv2);
            op[i] = t;
        }
        __syncthreads();   // done with this pass's Ks/Vs before next pass
    }
}

// ---------------------------------------------------------------------------
extern "C" void kernel_launch(void* const* d_in, const int* in_sizes, int n_in,
                              void* d_out, int out_size)
{
    const float* hidden = (const float*)d_in[0];
    const float* amask  = (const float*)d_in[1];
    const float* w_attn = (const float*)d_in[2];
    const float* b_attn = (const float*)d_in[3];
    const float* w_proj = (const float*)d_in[4];
    const float* b_proj = (const float*)d_in[5];
    float* out = (float*)d_out;

    float *qkv, *attn;
    cudaGetSymbolAddress((void**)&qkv,  g_qkv);
    cudaGetSymbolAddress((void**)&attn, g_attn);

    const int M = BS * SEQ;   // 4096

    gemm_bias_kernel<<<dim3(QKV3 / 128, M / 128), 256>>>(hidden, w_attn, b_attn, qkv, M, QKV3, NX);

    // 8 x 12 x 2 = 192 CTAs, each does exactly 17 key-tiles (balanced)
    attn_kernel<<<dim3(SEQ / 128 / 2, NHEAD, BS), 128>>>(qkv, amask, attn);

    gemm_bias_kernel<<<dim3(NX / 128, M / 128), 256>>>(attn, w_proj, b_proj, out, M, NX, NX);
}